// round 1
// baseline (speedup 1.0000x reference)
#include <cuda_runtime.h>

// ---------------------------------------------------------------------------
// GCN: 4 graph-conv layers + policy/value heads.
// Strategy: build CSR (sorted by dst) once per launch, then each layer is
//   agg[v] = norm_dst[v] * sum_{u in N_in(v)} hs[u]        (gather, no atomics)
//   hs     = relu(agg @ W + b) * norm_src                  (fused GEMM epilogue)
// Final layer writes raw h3 (64 wide); heads read h3.
// ---------------------------------------------------------------------------

constexpr int NN = 50000;
constexpr int NE = 800000;
constexpr int F  = 128;
constexpr int C3 = 64;

__device__ int   g_outdeg[NN];
__device__ int   g_indeg[NN];
__device__ float g_nsrc[NN];
__device__ float g_ndst[NN];
__device__ int   g_rowptr[NN + 1];
__device__ int   g_cursor[NN];
__device__ int   g_esrc[NE];
__device__ float g_hs[(size_t)NN * F];    // scaled features (gather source)
__device__ float g_agg[(size_t)NN * F];   // aggregated * norm_dst (GEMM input)
__device__ float g_h3[(size_t)NN * C3];   // final layer output
__device__ float g_mN[C3];

// --------------------------- setup kernels --------------------------------

__global__ void k_zero() {
    int i = blockIdx.x * blockDim.x + threadIdx.x;
    if (i < NN) { g_outdeg[i] = 0; g_indeg[i] = 0; }
    if (i < C3) g_mN[i] = 0.0f;
}

__global__ void k_hist(const int* __restrict__ src, const int* __restrict__ dst) {
    int e = blockIdx.x * blockDim.x + threadIdx.x;
    if (e < NE) {
        atomicAdd(&g_outdeg[src[e]], 1);
        atomicAdd(&g_indeg[dst[e]], 1);
    }
}

// Single-block exclusive scan of in-degrees -> rowptr, cursor.
__global__ void k_scan() {
    __shared__ int s[1024];
    int carry = 0;
    for (int base = 0; base < NN; base += 1024) {
        int i = base + (int)threadIdx.x;
        int v = (i < NN) ? g_indeg[i] : 0;
        s[threadIdx.x] = v;
        __syncthreads();
        for (int off = 1; off < 1024; off <<= 1) {
            int t = (threadIdx.x >= (unsigned)off) ? s[threadIdx.x - off] : 0;
            __syncthreads();
            s[threadIdx.x] += t;
            __syncthreads();
        }
        if (i < NN) {
            int excl = carry + s[threadIdx.x] - v;
            g_rowptr[i] = excl;
            g_cursor[i] = excl;
        }
        carry += s[1023];
        __syncthreads();
    }
    if (threadIdx.x == 0) g_rowptr[NN] = carry;
}

__global__ void k_norm() {
    int i = blockIdx.x * blockDim.x + threadIdx.x;
    if (i < NN) {
        g_nsrc[i] = rsqrtf((float)max(g_outdeg[i], 1));
        g_ndst[i] = rsqrtf((float)max(g_indeg[i], 1));
    }
}

__global__ void k_fill(const int* __restrict__ src, const int* __restrict__ dst) {
    int e = blockIdx.x * blockDim.x + threadIdx.x;
    if (e < NE) {
        int p = atomicAdd(&g_cursor[dst[e]], 1);
        g_esrc[p] = src[e];
    }
}

__global__ void k_scale0(const float* __restrict__ feats) {
    int i = blockIdx.x * blockDim.x + threadIdx.x;   // float4 index
    constexpr int TOT = NN * F / 4;
    if (i < TOT) {
        int node = i / (F / 4);
        float s = g_nsrc[node];
        float4 x = ((const float4*)feats)[i];
        x.x *= s; x.y *= s; x.z *= s; x.w *= s;
        ((float4*)g_hs)[i] = x;
    }
}

// --------------------------- aggregation ----------------------------------
// One warp per node; lane owns one float4 (4 feats). Warp reads 512B
// contiguous per edge -> fully coalesced; h array is L2-resident.

__global__ void k_agg() {
    int v = blockIdx.x * (blockDim.x >> 5) + (threadIdx.x >> 5);
    if (v >= NN) return;
    int lane = threadIdx.x & 31;
    int beg = g_rowptr[v], end = g_rowptr[v + 1];
    const float4* hs4 = (const float4*)g_hs;
    float4 a0 = make_float4(0.f, 0.f, 0.f, 0.f);
    float4 a1 = make_float4(0.f, 0.f, 0.f, 0.f);
    int e = beg;
    for (; e + 1 < end; e += 2) {
        int u0 = g_esrc[e];
        int u1 = g_esrc[e + 1];
        float4 x0 = hs4[u0 * 32 + lane];
        float4 x1 = hs4[u1 * 32 + lane];
        a0.x += x0.x; a0.y += x0.y; a0.z += x0.z; a0.w += x0.w;
        a1.x += x1.x; a1.y += x1.y; a1.z += x1.z; a1.w += x1.w;
    }
    if (e < end) {
        int u = g_esrc[e];
        float4 x = hs4[u * 32 + lane];
        a0.x += x.x; a0.y += x.y; a0.z += x.z; a0.w += x.w;
    }
    float nd = g_ndst[v];
    float4 o;
    o.x = (a0.x + a1.x) * nd;
    o.y = (a0.y + a1.y) * nd;
    o.z = (a0.z + a1.z) * nd;
    o.w = (a0.w + a1.w) * nd;
    ((float4*)g_agg)[v * 32 + lane] = o;
}

// ------------------------------ GEMM ---------------------------------------
// out[NN x COUT] = g_agg[NN x 128] @ W[128 x COUT] + b, fused relu/scale.
// Block: 256 threads, 32 rows. Thread: RPT rows x 4 cols in registers.

template <int COUT, bool RELU, bool SCALE, bool TO_H3>
__global__ void k_gemm(const float* __restrict__ W, const float* __restrict__ b) {
    constexpr int K   = 128;
    constexpr int RB  = 32;
    constexpr int CG  = COUT / 4;        // column groups of 4
    constexpr int RG  = 256 / CG;        // row groups
    constexpr int RPT = RB / RG;         // rows per thread
    __shared__ float sA[RB * K];

    int row0 = blockIdx.x * RB;
    const float4* A4 = (const float4*)g_agg;
    float4* s4 = (float4*)sA;
    #pragma unroll
    for (int i = threadIdx.x; i < RB * K / 4; i += 256) {
        int r  = i / (K / 4);
        int gr = row0 + r;
        s4[i] = (gr < NN) ? A4[gr * (K / 4) + (i % (K / 4))]
                          : make_float4(0.f, 0.f, 0.f, 0.f);
    }
    __syncthreads();

    int cg = threadIdx.x % CG;
    int rg = threadIdx.x / CG;

    float acc[RPT][4];
    #pragma unroll
    for (int r = 0; r < RPT; r++)
        #pragma unroll
        for (int j = 0; j < 4; j++) acc[r][j] = 0.f;

    const float4* W4 = (const float4*)W;
    #pragma unroll 8
    for (int k = 0; k < K; k++) {
        float4 w = W4[k * CG + cg];
        #pragma unroll
        for (int r = 0; r < RPT; r++) {
            float a = sA[(rg * RPT + r) * K + k];
            acc[r][0] += a * w.x;
            acc[r][1] += a * w.y;
            acc[r][2] += a * w.z;
            acc[r][3] += a * w.w;
        }
    }

    float4 bb = ((const float4*)b)[cg];
    #pragma unroll
    for (int r = 0; r < RPT; r++) {
        int gr = row0 + rg * RPT + r;
        if (gr < NN) {
            float4 o;
            o.x = acc[r][0] + bb.x;
            o.y = acc[r][1] + bb.y;
            o.z = acc[r][2] + bb.z;
            o.w = acc[r][3] + bb.w;
            if (RELU) {
                o.x = fmaxf(o.x, 0.f); o.y = fmaxf(o.y, 0.f);
                o.z = fmaxf(o.z, 0.f); o.w = fmaxf(o.w, 0.f);
            }
            if (SCALE) {
                float s = g_nsrc[gr];
                o.x *= s; o.y *= s; o.z *= s; o.w *= s;
            }
            if (TO_H3) ((float4*)g_h3)[gr * (COUT / 4) + cg] = o;
            else       ((float4*)g_hs)[gr * (COUT / 4) + cg] = o;
        }
    }
}

// ------------------------------ heads --------------------------------------

__global__ void k_colsum() {
    int c = threadIdx.x;                 // 64 threads
    int base = blockIdx.x * 256;
    int end = min(base + 256, NN);
    float s = 0.f;
    for (int r = base; r < end; r++) s += g_h3[(size_t)r * C3 + c];
    atomicAdd(&g_mN[c], s);
}

__global__ void k_pi(const float* __restrict__ Wp, const float* __restrict__ bp,
                     float* __restrict__ out) {
    int v = blockIdx.x * (blockDim.x >> 5) + (threadIdx.x >> 5);
    if (v >= NN) return;
    int lane = threadIdx.x & 31;
    float2 h = ((const float2*)g_h3)[v * 32 + lane];
    float2 w = ((const float2*)Wp)[lane];
    float p = h.x * w.x + h.y * w.y;
    #pragma unroll
    for (int off = 16; off; off >>= 1) p += __shfl_xor_sync(0xffffffff, p, off);
    if (lane == 0) out[v] = p + bp[0];
}

__global__ void k_v(const float* __restrict__ Wv, const float* __restrict__ bv,
                    float* __restrict__ out) {
    int lane = threadIdx.x & 31;
    float2 m = ((const float2*)g_mN)[lane];
    float2 w = ((const float2*)Wv)[lane];
    float p = m.x * w.x + m.y * w.y;
    #pragma unroll
    for (int off = 16; off; off >>= 1) p += __shfl_xor_sync(0xffffffff, p, off);
    if (lane == 0) out[NN] = p + bv[0];
}

// --------------------------- launch ----------------------------------------

extern "C" void kernel_launch(void* const* d_in, const int* in_sizes, int n_in,
                              void* d_out, int out_size) {
    const float* feats = (const float*)d_in[0];
    const int*   src   = (const int*)d_in[1];
    const int*   dst   = (const int*)d_in[2];
    const float* W0 = (const float*)d_in[3];  const float* b0 = (const float*)d_in[4];
    const float* W1 = (const float*)d_in[5];  const float* b1 = (const float*)d_in[6];
    const float* W2 = (const float*)d_in[7];  const float* b2 = (const float*)d_in[8];
    const float* W3 = (const float*)d_in[9];  const float* b3 = (const float*)d_in[10];
    const float* Wp = (const float*)d_in[11]; const float* bp = (const float*)d_in[12];
    const float* Wv = (const float*)d_in[13]; const float* bv = (const float*)d_in[14];
    float* out = (float*)d_out;

    k_zero<<<(NN + 255) / 256, 256>>>();
    k_hist<<<(NE + 255) / 256, 256>>>(src, dst);
    k_scan<<<1, 1024>>>();
    k_norm<<<(NN + 255) / 256, 256>>>();
    k_fill<<<(NE + 255) / 256, 256>>>(src, dst);
    k_scale0<<<(NN * F / 4 + 255) / 256, 256>>>(feats);

    const int aggGrid  = (NN + 7) / 8;      // 8 warps/block
    const int gemmGrid = (NN + 31) / 32;

    k_agg<<<aggGrid, 256>>>();
    k_gemm<128, true,  true,  false><<<gemmGrid, 256>>>(W0, b0);
    k_agg<<<aggGrid, 256>>>();
    k_gemm<128, true,  true,  false><<<gemmGrid, 256>>>(W1, b1);
    k_agg<<<aggGrid, 256>>>();
    k_gemm<128, true,  true,  false><<<gemmGrid, 256>>>(W2, b2);
    k_agg<<<aggGrid, 256>>>();
    k_gemm<64,  false, false, true ><<<gemmGrid, 256>>>(W3, b3);

    k_colsum<<<(NN + 255) / 256, 64>>>();
    k_pi<<<aggGrid, 256>>>(Wp, bp, out);
    k_v<<<1, 32>>>(Wv, bv, out);
}